// round 2
// baseline (speedup 1.0000x reference)
#include <cuda_runtime.h>

#define Bc 4
#define Lc 2048
#define Hc 8
#define Vc 64
#define HVc 512
#define TQ 32
#define TK 32
#define NTHREADS 256

// smem layout (floats):
// s_q:    [0,96)      query positions, 32 q * 3
// s_ils:  [96,104)    1/ls^2 per head
// s_kx:   [104,136)
// s_ky:   [136,168)
// s_kz:   [168,200)
// s_ms:   [200,232)   mask factor 0/1
// s_w:    [232,9448)  weights, stride 9 per (k,q) for bank-conflict-free access
// s_v:    [9448,25832) values tile 32k x 512 (float4-aligned: 9448%4==0)
#define OFF_Q   0
#define OFF_ILS 96
#define OFF_KX  104
#define OFF_KY  136
#define OFF_KZ  168
#define OFF_MS  200
#define OFF_W   232
#define OFF_V   9448
#define SMEM_FLOATS 25832

// normalized attended output [B, Lq, H*V], consumed by projection GEMM
__device__ float g_att[Bc * Lc * HVc];

__global__ __launch_bounds__(NTHREADS, 2)
void attend_kernel(const float* __restrict__ qpos,
                   const float* __restrict__ kpos,
                   const float* __restrict__ values,
                   const int*   __restrict__ mask,
                   const float* __restrict__ ls)
{
    extern __shared__ float sm[];
    float*  s_q   = sm + OFF_Q;
    float*  s_ils = sm + OFF_ILS;
    float*  s_kx  = sm + OFF_KX;
    float*  s_ky  = sm + OFF_KY;
    float*  s_kz  = sm + OFF_KZ;
    float*  s_ms  = sm + OFF_MS;
    float*  s_w   = sm + OFF_W;
    float4* s_v4  = (float4*)(sm + OFF_V);

    const int tid = threadIdx.x;
    const int b  = blockIdx.x >> 6;     // 64 q-tiles per batch
    const int qt = blockIdx.x & 63;

    // one-time loads
    if (tid < 96) s_q[tid] = qpos[(b * Lc + qt * TQ) * 3 + tid];
    if (tid < 8) { float l = ls[tid]; s_ils[tid] = 1.0f / (l * l); }

    // thread mapping for accumulate phase:
    //   vc = v-chunk (4 chunks of 16), h = head, qg = query group (4 q each)
    const int vc = tid & 3;
    const int h  = (tid >> 2) & 7;
    const int qg = tid >> 5;

    float acc[4][16];
    #pragma unroll
    for (int i = 0; i < 4; i++)
        #pragma unroll
        for (int j = 0; j < 16; j++) acc[i][j] = 0.0f;
    float den[4] = {1e-5f, 1e-5f, 1e-5f, 1e-5f};

    const float4* vals4 = (const float4*)values;

    for (int k0 = 0; k0 < Lc; k0 += TK) {
        __syncthreads();   // protect s_w / s_v from previous iteration's readers

        if (tid < TK) {
            const float* kp = kpos + (b * Lc + k0 + tid) * 3;
            s_kx[tid] = kp[0];
            s_ky[tid] = kp[1];
            s_kz[tid] = kp[2];
            s_ms[tid] = mask[b * Lc + k0 + tid] ? 0.0f : 1.0f;
        }
        // values tile: 32 keys * 512 floats contiguous -> coalesced float4
        {
            const int vbase = (b * Lc + k0) * (HVc / 4);
            #pragma unroll
            for (int i = 0; i < 16; i++)
                s_v4[tid + i * NTHREADS] = vals4[vbase + tid + i * NTHREADS];
        }
        __syncthreads();

        // ---- phase A: weights w[k][q][h] = mask * exp(-d2/ls^2) ----
        #pragma unroll
        for (int j = 0; j < 4; j++) {
            const int p = tid + j * NTHREADS;
            const int q = p & 31;     // consecutive across lanes -> conflict-free STS
            const int k = p >> 5;     // warp-uniform -> uniform mask branch
            const float dx = s_q[q * 3 + 0] - s_kx[k];
            const float dy = s_q[q * 3 + 1] - s_ky[k];
            const float dz = s_q[q * 3 + 2] - s_kz[k];
            const float d2 = dx * dx + dy * dy + dz * dz;
            float* wp = s_w + (k * TQ + q) * 9;
            if (s_ms[k] != 0.0f) {
                #pragma unroll
                for (int hh = 0; hh < 8; hh++)
                    wp[hh] = __expf(-d2 * s_ils[hh]);
            } else {
                #pragma unroll
                for (int hh = 0; hh < 8; hh++)
                    wp[hh] = 0.0f;
            }
        }
        __syncthreads();

        // ---- phase B: accumulate (4 q) x (head h) x (16 v) per thread ----
        #pragma unroll 4
        for (int k = 0; k < TK; k++) {
            float w0 = s_w[(k * TQ + qg * 4 + 0) * 9 + h];
            float w1 = s_w[(k * TQ + qg * 4 + 1) * 9 + h];
            float w2 = s_w[(k * TQ + qg * 4 + 2) * 9 + h];
            float w3 = s_w[(k * TQ + qg * 4 + 3) * 9 + h];
            den[0] += w0; den[1] += w1; den[2] += w2; den[3] += w3;

            const int vb = k * (HVc / 4) + h * 16 + vc * 4;
            float4 v0 = s_v4[vb + 0];
            float4 v1 = s_v4[vb + 1];
            float4 v2 = s_v4[vb + 2];
            float4 v3 = s_v4[vb + 3];

            #pragma unroll
            for (int i = 0; i < 4; i++) {
                const float w = (i == 0) ? w0 : (i == 1) ? w1 : (i == 2) ? w2 : w3;
                acc[i][0]  += w * v0.x;  acc[i][1]  += w * v0.y;
                acc[i][2]  += w * v0.z;  acc[i][3]  += w * v0.w;
                acc[i][4]  += w * v1.x;  acc[i][5]  += w * v1.y;
                acc[i][6]  += w * v1.z;  acc[i][7]  += w * v1.w;
                acc[i][8]  += w * v2.x;  acc[i][9]  += w * v2.y;
                acc[i][10] += w * v2.z;  acc[i][11] += w * v2.w;
                acc[i][12] += w * v3.x;  acc[i][13] += w * v3.y;
                acc[i][14] += w * v3.z;  acc[i][15] += w * v3.w;
            }
        }
    }

    // ---- epilogue: normalize and write attended ----
    float4* att4 = (float4*)g_att;
    #pragma unroll
    for (int i = 0; i < 4; i++) {
        const int q = qt * TQ + qg * 4 + i;
        const float inv = 1.0f / den[i];
        const int base = ((b * Lc + q) * HVc + h * Vc + vc * 16) >> 2;
        #pragma unroll
        for (int jj = 0; jj < 4; jj++) {
            att4[base + jj] = make_float4(acc[i][jj * 4 + 0] * inv,
                                          acc[i][jj * 4 + 1] * inv,
                                          acc[i][jj * 4 + 2] * inv,
                                          acc[i][jj * 4 + 3] * inv);
        }
    }
}

// ---- projection: out[8192,512] = g_att[8192,512] @ w_out[512,512]^T ----
#define BM 64
#define BN 64
#define BK 16

__global__ __launch_bounds__(256)
void proj_kernel(const float* __restrict__ W, float* __restrict__ out)
{
    __shared__ float As[BM][BK + 1];
    __shared__ float Ws[BN][BK + 1];

    const int tid = threadIdx.x;
    const int m0 = blockIdx.y * BM;
    const int n0 = blockIdx.x * BN;
    const int tx = tid & 15;       // n sub-tile
    const int ty = tid >> 4;       // m sub-tile

    const int lrow = tid >> 2;            // 0..63
    const int lk   = (tid & 3) * 4;       // 0,4,8,12

    float acc[4][4];
    #pragma unroll
    for (int i = 0; i < 4; i++)
        #pragma unroll
        for (int j = 0; j < 4; j++) acc[i][j] = 0.0f;

    for (int k0 = 0; k0 < HVc; k0 += BK) {
        float4 a = *(const float4*)&g_att[(m0 + lrow) * HVc + k0 + lk];
        float4 w = *(const float4*)&W[(n0 + lrow) * HVc + k0 + lk];
        As[lrow][lk + 0] = a.x; As[lrow][lk + 1] = a.y;
        As[lrow][lk + 2] = a.z; As[lrow][lk + 3] = a.w;
        Ws[lrow][lk + 0] = w.x; Ws[lrow][lk + 1] = w.y;
        Ws[lrow][lk + 2] = w.z; Ws[lrow][lk + 3] = w.w;
        __syncthreads();

        #pragma unroll
        for (int k = 0; k < BK; k++) {
            float av[4], bv[4];
            #pragma unroll
            for (int i = 0; i < 4; i++) av[i] = As[ty * 4 + i][k];
            #pragma unroll
            for (int j = 0; j < 4; j++) bv[j] = Ws[tx * 4 + j][k];
            #pragma unroll
            for (int i = 0; i < 4; i++)
                #pragma unroll
                for (int j = 0; j < 4; j++)
                    acc[i][j] += av[i] * bv[j];
        }
        __syncthreads();
    }

    #pragma unroll
    for (int i = 0; i < 4; i++) {
        float4 r = make_float4(acc[i][0], acc[i][1], acc[i][2], acc[i][3]);
        *(float4*)&out[(m0 + ty * 4 + i) * HVc + n0 + tx * 4] = r;
    }
}

extern "C" void kernel_launch(void* const* d_in, const int* in_sizes, int n_in,
                              void* d_out, int out_size)
{
    const float* qpos   = (const float*)d_in[0];
    const float* kpos   = (const float*)d_in[1];
    const float* values = (const float*)d_in[2];
    const int*   mask   = (const int*)  d_in[3];
    const float* ls     = (const float*)d_in[4];
    const float* w_out  = (const float*)d_in[5];
    float* out = (float*)d_out;

    const int smem_bytes = SMEM_FLOATS * (int)sizeof(float);
    cudaFuncSetAttribute(attend_kernel,
                         cudaFuncAttributeMaxDynamicSharedMemorySize, smem_bytes);

    attend_kernel<<<Bc * (Lc / TQ), NTHREADS, smem_bytes>>>(qpos, kpos, values, mask, ls);
    proj_kernel<<<dim3(HVc / BN, (Bc * Lc) / BM), 256>>>(w_out, out);
}